// round 2
// baseline (speedup 1.0000x reference)
#include <cuda_runtime.h>

// ---------------------------------------------------------------------------
// CharacterEmbeddingLayer: char-CNN (windows 2..5, 100 filters each, tanh+maxpool)
// -> 400-dim concat -> proj to 128 -> 2-layer highway.
// B=64, S=400, W=16, D=64, VOCAB=96, HID=128. Tokens = 25600.
//
// Kernel 1 (conv_kernel): warp-per-token. X tile [16x64] in smem, filter slices
// [100x64] staged transposed in smem (stride 129, conflict-free). Each lane owns
// 4 filters; accumulators acc[L][4] in registers. max-pool BEFORE tanh
// (monotonicity) -> only 400 tanh/token.
// Kernel 2 (head_kernel): 32 tokens/CTA; proj (K=400) + both highway layers
// fused, weights chunk-staged in smem with odd-stride padding.
// ---------------------------------------------------------------------------

#define NTOK 25600

__device__ float g_conv[NTOK * 400];   // 40.96 MB scratch (static device global)

__device__ __forceinline__ float my_tanh(float x) {
    float ax = fabsf(x);
    float e  = __expf(2.0f * ax);           // ax large -> inf -> r -> 1
    float r  = 1.0f - 2.0f / (e + 1.0f);
    return copysignf(r, x);
}

// ---------------------------------------------------------------------------
// Conv branch for one window size W. Warp handles one token.
// Ftr smem layout: Ftr[k*129 + f], f in [0,128) (f>=100 zero-padded).
// ---------------------------------------------------------------------------
template<int W>
__device__ __forceinline__ void conv_win(
    const float* __restrict__ filt,   // [100][W*64] row-major
    const float* Xtok,                // smem, [16][64] for this warp's token
    float* Ftr,                       // smem, 64*129 floats (CTA-shared)
    float* __restrict__ outp,         // g_conv row + window offset
    int lane, int tid)
{
    constexpr int L = 17 - W;
    float acc[L][4];
#pragma unroll
    for (int l = 0; l < L; ++l)
#pragma unroll
        for (int fi = 0; fi < 4; ++fi) acc[l][fi] = 0.0f;

    for (int j = 0; j < W; ++j) {
        __syncthreads();   // previous Ftr consumers done
        for (int i = tid; i < 64 * 128; i += 256) {
            int f = i >> 6, k = i & 63;
            Ftr[k * 129 + f] = (f < 100) ? filt[f * (W * 64) + j * 64 + k] : 0.0f;
        }
        __syncthreads();
#pragma unroll 2
        for (int k4 = 0; k4 < 16; ++k4) {
            float fv[4][4];
#pragma unroll
            for (int kk = 0; kk < 4; ++kk)
#pragma unroll
                for (int fi = 0; fi < 4; ++fi)
                    fv[kk][fi] = Ftr[(k4 * 4 + kk) * 129 + fi * 32 + lane];
#pragma unroll
            for (int l = 0; l < L; ++l) {
                float4 x = *reinterpret_cast<const float4*>(Xtok + (l + j) * 64 + k4 * 4);
#pragma unroll
                for (int fi = 0; fi < 4; ++fi) {
                    acc[l][fi] = fmaf(x.x, fv[0][fi], acc[l][fi]);
                    acc[l][fi] = fmaf(x.y, fv[1][fi], acc[l][fi]);
                    acc[l][fi] = fmaf(x.z, fv[2][fi], acc[l][fi]);
                    acc[l][fi] = fmaf(x.w, fv[3][fi], acc[l][fi]);
                }
            }
        }
    }
    // max over positions, THEN tanh (monotone)
#pragma unroll
    for (int fi = 0; fi < 4; ++fi) {
        float m = acc[0][fi];
#pragma unroll
        for (int l = 1; l < L; ++l) m = fmaxf(m, acc[l][fi]);
        int f = fi * 32 + lane;
        if (f < 100) outp[f] = my_tanh(m);
    }
}

__global__ __launch_bounds__(256) void conv_kernel(
    const int*   __restrict__ idxs,   // [25600*16]
    const float* __restrict__ vecs,   // [96][64]
    const float* __restrict__ f2, const float* __restrict__ f3,
    const float* __restrict__ f4, const float* __restrict__ f5)
{
    extern __shared__ float smem[];
    int*   sIdx = reinterpret_cast<int*>(smem);  // 128 ints
    float* Xs   = smem + 128;                    // 8*16*64 = 8192
    float* Ftr  = Xs + 8192;                     // 64*129  = 8256

    int tid  = threadIdx.x;
    int tok0 = blockIdx.x * 8;

    if (tid < 128) sIdx[tid] = idxs[tok0 * 16 + tid];
    __syncthreads();

    // gather embeddings: 8 tokens x 16 chars x 64 dims, float4
    for (int i = tid; i < 128 * 16; i += 256) {
        int tp = i >> 4, k4 = i & 15;
        int ci = sIdx[tp];
        float4 v = *reinterpret_cast<const float4*>(vecs + ci * 64 + k4 * 4);
        *reinterpret_cast<float4*>(Xs + tp * 64 + k4 * 4) = v;
    }
    // (conv_win's leading __syncthreads orders Xs writes before reads)

    int warp = tid >> 5, lane = tid & 31;
    const float* Xtok = Xs + warp * 1024;
    float* outp = g_conv + (tok0 + warp) * 400;

    conv_win<2>(f2, Xtok, Ftr, outp,       lane, tid);
    conv_win<3>(f3, Xtok, Ftr, outp + 100, lane, tid);
    conv_win<4>(f4, Xtok, Ftr, outp + 200, lane, tid);
    conv_win<5>(f5, Xtok, Ftr, outp + 300, lane, tid);
}

// ---------------------------------------------------------------------------
// Head: proj (400->128) + two highway layers, fused per 32-token block.
// Thread map: 8 groups (warps) x 4 tokens; lane -> h in {lane, +32, +64, +96}.
// ---------------------------------------------------------------------------
__global__ __launch_bounds__(256) void head_kernel(
    const float* __restrict__ wp,
    const float* __restrict__ tw0, const float* __restrict__ tb0,
    const float* __restrict__ tw1, const float* __restrict__ tb1,
    const float* __restrict__ gw0, const float* __restrict__ gb0,
    const float* __restrict__ gw1, const float* __restrict__ gb1,
    float* __restrict__ out)
{
    extern __shared__ float smem[];
    float* sA = smem;            // 32*400 = 12800
    float* sB = sA + 12800;      // 8256 (weight chunks, stride-129 padded)
    float* sX = sB + 8256;       // 32*128 = 4096

    int tid  = threadIdx.x;
    int lane = tid & 31, grp = tid >> 5;
    int tok0 = blockIdx.x * 32;

    // load conv features block (contiguous)
    for (int i = tid; i < 3200; i += 256)
        reinterpret_cast<float4*>(sA)[i] =
            reinterpret_cast<const float4*>(g_conv + tok0 * 400)[i];

    float xr[4][4];

    // ---- projection: x = A @ wp^T ----
    {
        float acc[4][4];
#pragma unroll
        for (int tt = 0; tt < 4; ++tt)
#pragma unroll
            for (int hi = 0; hi < 4; ++hi) acc[tt][hi] = 0.0f;

        for (int k0 = 0; k0 < 400; k0 += 40) {
            __syncthreads();   // also orders the sA load on first iteration
            for (int i = tid; i < 128 * 40; i += 256) {
                int h = i / 40, kk = i - h * 40;
                sB[kk * 129 + h] = wp[h * 400 + k0 + kk];
            }
            __syncthreads();
            for (int kk = 0; kk < 40; ++kk) {
                float w0 = sB[kk * 129 + lane];
                float w1 = sB[kk * 129 + lane + 32];
                float w2 = sB[kk * 129 + lane + 64];
                float w3 = sB[kk * 129 + lane + 96];
#pragma unroll
                for (int tt = 0; tt < 4; ++tt) {
                    float a = sA[(grp * 4 + tt) * 400 + k0 + kk];
                    acc[tt][0] = fmaf(a, w0, acc[tt][0]);
                    acc[tt][1] = fmaf(a, w1, acc[tt][1]);
                    acc[tt][2] = fmaf(a, w2, acc[tt][2]);
                    acc[tt][3] = fmaf(a, w3, acc[tt][3]);
                }
            }
        }
#pragma unroll
        for (int tt = 0; tt < 4; ++tt)
#pragma unroll
            for (int hi = 0; hi < 4; ++hi) {
                xr[tt][hi] = acc[tt][hi];
                sX[(grp * 4 + tt) * 128 + lane + 32 * hi] = acc[tt][hi];
            }
        __syncthreads();
    }

    // ---- highway layers ----
    auto layer = [&](const float* twq, const float* tbq,
                     const float* gwq, const float* gbq) {
        float at[4][4], ag[4][4];
#pragma unroll
        for (int tt = 0; tt < 4; ++tt)
#pragma unroll
            for (int hi = 0; hi < 4; ++hi) { at[tt][hi] = 0.0f; ag[tt][hi] = 0.0f; }

        for (int k0 = 0; k0 < 128; k0 += 32) {
            __syncthreads();
            for (int i = tid; i < 128 * 32; i += 256) {
                int h = i >> 5, kk = i & 31;
                sB[kk * 129 + h]        = twq[h * 128 + k0 + kk];
                sB[4128 + kk * 129 + h] = gwq[h * 128 + k0 + kk];
            }
            __syncthreads();
            for (int kk = 0; kk < 32; ++kk) {
                float wt0 = sB[kk * 129 + lane];
                float wt1 = sB[kk * 129 + lane + 32];
                float wt2 = sB[kk * 129 + lane + 64];
                float wt3 = sB[kk * 129 + lane + 96];
                float wg0 = sB[4128 + kk * 129 + lane];
                float wg1 = sB[4128 + kk * 129 + lane + 32];
                float wg2 = sB[4128 + kk * 129 + lane + 64];
                float wg3 = sB[4128 + kk * 129 + lane + 96];
#pragma unroll
                for (int tt = 0; tt < 4; ++tt) {
                    float a = sX[(grp * 4 + tt) * 128 + k0 + kk];
                    at[tt][0] = fmaf(a, wt0, at[tt][0]);
                    at[tt][1] = fmaf(a, wt1, at[tt][1]);
                    at[tt][2] = fmaf(a, wt2, at[tt][2]);
                    at[tt][3] = fmaf(a, wt3, at[tt][3]);
                    ag[tt][0] = fmaf(a, wg0, ag[tt][0]);
                    ag[tt][1] = fmaf(a, wg1, ag[tt][1]);
                    ag[tt][2] = fmaf(a, wg2, ag[tt][2]);
                    ag[tt][3] = fmaf(a, wg3, ag[tt][3]);
                }
            }
        }
        float tb4[4], gb4[4];
#pragma unroll
        for (int hi = 0; hi < 4; ++hi) {
            tb4[hi] = tbq[lane + 32 * hi];
            gb4[hi] = gbq[lane + 32 * hi];
        }
#pragma unroll
        for (int tt = 0; tt < 4; ++tt)
#pragma unroll
            for (int hi = 0; hi < 4; ++hi) {
                float g = 1.0f / (1.0f + __expf(-(ag[tt][hi] + gb4[hi])));
                float t = fmaxf(at[tt][hi] + tb4[hi], 0.0f);
                xr[tt][hi] = g * t + (1.0f - g) * xr[tt][hi];
            }
        __syncthreads();   // everyone done reading old sX
#pragma unroll
        for (int tt = 0; tt < 4; ++tt)
#pragma unroll
            for (int hi = 0; hi < 4; ++hi)
                sX[(grp * 4 + tt) * 128 + lane + 32 * hi] = xr[tt][hi];
        __syncthreads();
    };

    layer(tw0, tb0, gw0, gb0);
    layer(tw1, tb1, gw1, gb1);

#pragma unroll
    for (int tt = 0; tt < 4; ++tt)
#pragma unroll
        for (int hi = 0; hi < 4; ++hi)
            out[(tok0 + grp * 4 + tt) * 128 + lane + 32 * hi] = xr[tt][hi];
}

// ---------------------------------------------------------------------------
extern "C" void kernel_launch(void* const* d_in, const int* in_sizes, int n_in,
                              void* d_out, int out_size) {
    const int*   idxs = (const int*)  d_in[0];
    const float* vecs = (const float*)d_in[1];
    const float* f2   = (const float*)d_in[2];
    const float* f3   = (const float*)d_in[3];
    const float* f4   = (const float*)d_in[4];
    const float* f5   = (const float*)d_in[5];
    const float* wp   = (const float*)d_in[6];
    const float* tw0  = (const float*)d_in[7];
    const float* tb0  = (const float*)d_in[8];
    const float* tw1  = (const float*)d_in[9];
    const float* tb1  = (const float*)d_in[10];
    const float* gw0  = (const float*)d_in[11];
    const float* gb0  = (const float*)d_in[12];
    const float* gw1  = (const float*)d_in[13];
    const float* gb1  = (const float*)d_in[14];
    float* out = (float*)d_out;

    size_t smem1 = (size_t)(128 + 8192 + 8256) * 4;          // 66,304 B
    size_t smem2 = (size_t)(12800 + 8256 + 4096) * 4;        // 100,608 B
    cudaFuncSetAttribute(conv_kernel, cudaFuncAttributeMaxDynamicSharedMemorySize, (int)smem1);
    cudaFuncSetAttribute(head_kernel, cudaFuncAttributeMaxDynamicSharedMemorySize, (int)smem2);

    conv_kernel<<<3200, 256, smem1>>>(idxs, vecs, f2, f3, f4, f5);
    head_kernel<<<800, 256, smem2>>>(wp, tw0, tb0, tw1, tb1,
                                     gw0, gb0, gw1, gb1, out);
}

// round 6
// speedup vs baseline: 1.6945x; 1.6945x over previous
#include <cuda_runtime.h>
#include <cstdint>

// ---------------------------------------------------------------------------
// CharacterEmbeddingLayer on GB300 (compute_103 PTX target -> no tcgen05;
// use classic mma.sync tf32 m16n8k8 tensor cores).
//
// Conv: per (token, window w): D[16 x 104] = A[16 x w*64] @ B[w*64 x 104]
//   A row l = X[l .. l+w-1][0..63] (contiguous rows in SMEM, stride 72)
//   B = filt_w^T, prepacked into mma fragment order (tf32-rounded) with a
//   k-permutation making every fragment load a contiguous LDS.64.
//   Epilogue in-fragment: max over valid rows l<L via shfl_xor, then tanh.
// Head: proj(400->128) + 2 highway layers (unchanged, known-good).
// ---------------------------------------------------------------------------

#define NTOK 25600
#define XSTR 72                 // X row stride (floats): banks = 8r+2c, conflict-free
#define XTOK (20 * XSTR)        // 20 rows per token (rows 16..19 zero pad)

// B fragment buffer offsets (float2 units) per window w=2..5
#define BOFF2 0
#define BOFF3 6656
#define BOFF4 16640
#define BOFF5 29952
#define BTOT  46592

__device__ float g_conv[NTOK * 400];                  // 40.96 MB scratch
__device__ __align__(16) float2 g_bfrag[BTOT];        // prepacked tf32 B fragments

// smem layout (bytes): sBF [133120] | Xs [92160] | sIdx [1024]
#define SM_BF   0
#define SM_XS   133120
#define SM_IDX  (133120 + 92160)
#define SM_TOT  (SM_IDX + 1024)   // 226304 <= 232448

__device__ __forceinline__ uint32_t f2tf(float x) {
    uint32_t u;
    asm("cvt.rna.tf32.f32 %0, %1;" : "=r"(u) : "f"(x));
    return u;
}

__device__ __forceinline__ void mma1688(float& d0, float& d1, float& d2, float& d3,
                                        uint32_t a0, uint32_t a1, uint32_t a2, uint32_t a3,
                                        uint32_t b0, uint32_t b1) {
    asm volatile(
        "mma.sync.aligned.m16n8k8.row.col.f32.tf32.tf32.f32 "
        "{%0,%1,%2,%3}, {%4,%5,%6,%7}, {%8,%9}, {%0,%1,%2,%3};"
        : "+f"(d0), "+f"(d1), "+f"(d2), "+f"(d3)
        : "r"(a0), "r"(a1), "r"(a2), "r"(a3), "r"(b0), "r"(b1));
}

__device__ __forceinline__ float my_tanh(float x) {
    float ax = fabsf(x);
    float e  = __expf(2.0f * ax);
    float r  = 1.0f - 2.0f / (e + 1.0f);
    return copysignf(r, x);
}

// ---------------------------------------------------------------------------
// Prep: pack filters into mma B-fragment order, tf32-rounded.
// Fragment layout: [ntile][kstep][lane] float2. Lane holds
// (b0,b1) = filt[f][ks*8 + 2t], filt[f][ks*8 + 2t + 1]; f = ntile*8 + lane/4,
// t = lane%4 (k-permutation: logical k c -> phys 2c, c+4 -> 2c+1).
// 52 blocks = 4 windows x 13 ntiles.
// ---------------------------------------------------------------------------
__global__ void prep_kernel(const float* __restrict__ f2, const float* __restrict__ f3,
                            const float* __restrict__ f4, const float* __restrict__ f5) {
    int b  = blockIdx.x;
    int wi = b / 13, n = b % 13;
    int W  = wi + 2;
    const float* fp = (wi == 0) ? f2 : (wi == 1) ? f3 : (wi == 2) ? f4 : f5;
    int woff = (wi == 0) ? BOFF2 : (wi == 1) ? BOFF3 : (wi == 2) ? BOFF4 : BOFF5;
    int K8 = W * 8;
    for (int i = threadIdx.x; i < K8 * 32; i += blockDim.x) {
        int ks = i >> 5, lane = i & 31;
        int t = lane & 3, f = n * 8 + (lane >> 2);
        float v0 = 0.0f, v1 = 0.0f;
        if (f < 100) {
            const float* src = fp + f * (W * 64) + ks * 8 + 2 * t;
            v0 = src[0]; v1 = src[1];
        }
        float2 o;
        o.x = __uint_as_float(f2tf(v0));
        o.y = __uint_as_float(f2tf(v1));
        g_bfrag[woff + (n * K8 + ks) * 32 + lane] = o;
    }
}

// ---------------------------------------------------------------------------
// One pass: ntiles [NT0, NT0+NTN) for window W, 2 tokens per warp.
// ---------------------------------------------------------------------------
template<int W, int NT0, int NTN>
__device__ __forceinline__ void conv_pass(
    const float2* __restrict__ sBF,
    const float* __restrict__ X0, const float* __restrict__ X1,
    int lane, float* __restrict__ g0, float* __restrict__ g1)
{
    constexpr int L  = 17 - W;
    constexpr int K8 = W * 8;
    int r = lane >> 2, t = lane & 3;

    float acc0[NTN][4], acc1[NTN][4];
#pragma unroll
    for (int n = 0; n < NTN; ++n)
#pragma unroll
        for (int q = 0; q < 4; ++q) { acc0[n][q] = 0.0f; acc1[n][q] = 0.0f; }

#pragma unroll 4
    for (int ks = 0; ks < K8; ++ks) {
        int off = (ks >> 3) * XSTR + (ks & 7) * 8;
        float2 xa0 = *(const float2*)(X0 + off);
        float2 xb0 = *(const float2*)(X0 + off + 8 * XSTR);
        float2 xa1 = *(const float2*)(X1 + off);
        float2 xb1 = *(const float2*)(X1 + off + 8 * XSTR);
        uint32_t a00 = f2tf(xa0.x), a01 = f2tf(xb0.x), a02 = f2tf(xa0.y), a03 = f2tf(xb0.y);
        uint32_t a10 = f2tf(xa1.x), a11 = f2tf(xb1.x), a12 = f2tf(xa1.y), a13 = f2tf(xb1.y);
#pragma unroll
        for (int n = 0; n < NTN; ++n) {
            float2 bf = sBF[((NT0 + n) * K8 + ks) * 32 + lane];
            uint32_t b0 = __float_as_uint(bf.x), b1 = __float_as_uint(bf.y);
            mma1688(acc0[n][0], acc0[n][1], acc0[n][2], acc0[n][3],
                    a00, a01, a02, a03, b0, b1);
            mma1688(acc1[n][0], acc1[n][1], acc1[n][2], acc1[n][3],
                    a10, a11, a12, a13, b0, b1);
        }
    }

    // max over rows (r always < L; r+8 valid iff r+8 < L), reduce across the
    // 8 lanes sharing t (xor 4,8,16), tanh, write.
    bool v2 = (r + 8) < L;
#pragma unroll
    for (int n = 0; n < NTN; ++n) {
        float m0 = v2 ? fmaxf(acc0[n][0], acc0[n][2]) : acc0[n][0];
        float m1 = v2 ? fmaxf(acc0[n][1], acc0[n][3]) : acc0[n][1];
        float p0 = v2 ? fmaxf(acc1[n][0], acc1[n][2]) : acc1[n][0];
        float p1 = v2 ? fmaxf(acc1[n][1], acc1[n][3]) : acc1[n][1];
#pragma unroll
        for (int o = 4; o <= 16; o <<= 1) {
            m0 = fmaxf(m0, __shfl_xor_sync(0xffffffffu, m0, o));
            m1 = fmaxf(m1, __shfl_xor_sync(0xffffffffu, m1, o));
            p0 = fmaxf(p0, __shfl_xor_sync(0xffffffffu, p0, o));
            p1 = fmaxf(p1, __shfl_xor_sync(0xffffffffu, p1, o));
        }
        int f = (NT0 + n) * 8 + 2 * t;
        if (r == 0 && f < 100) {
            *(float2*)(g0 + f) = make_float2(my_tanh(m0), my_tanh(m1));
            *(float2*)(g1 + f) = make_float2(my_tanh(p0), my_tanh(p1));
        }
    }
}

__global__ __launch_bounds__(256, 1) void conv_kernel(
    const int* __restrict__ idxs, const float* __restrict__ vecs)
{
    extern __shared__ __align__(16) char smem[];
    float2* sBF  = (float2*)(smem + SM_BF);
    float*  Xs   = (float*)(smem + SM_XS);
    int*    sIdx = (int*)(smem + SM_IDX);

    int tid  = threadIdx.x;
    int tok0 = blockIdx.x * 16;

    sIdx[tid] = idxs[tok0 * 16 + tid];
    __syncthreads();

    // gather X: 16 tokens x 20 rows (16 real + 4 zero) x 16 float4
    for (int i = tid; i < 16 * 20 * 16; i += 256) {
        int tok = i / 320, rem = i % 320, row = rem >> 4, e4 = rem & 15;
        float4 v = make_float4(0.f, 0.f, 0.f, 0.f);
        if (row < 16) {
            int ci = sIdx[tok * 16 + row];
            v = *(const float4*)(vecs + ci * 64 + e4 * 4);
        }
        *(float4*)(Xs + tok * XTOK + row * XSTR + e4 * 4) = v;
    }

    int warp = tid >> 5, lane = tid & 31;
    int r = lane >> 2, t = lane & 3;
    const float* X0 = Xs + (warp * 2 + 0) * XTOK + r * XSTR + 2 * t;
    const float* X1 = Xs + (warp * 2 + 1) * XTOK + r * XSTR + 2 * t;
    float* g0 = g_conv + (tok0 + warp * 2 + 0) * 400;
    float* g1 = g_conv + (tok0 + warp * 2 + 1) * 400;

    auto loadB = [&](int woffF2, int cntF2) {
        __syncthreads();                       // previous sBF consumers done (+X writes)
        const float4* s = (const float4*)(g_bfrag + woffF2);
        float4* d = (float4*)sBF;
        for (int i = tid; i < (cntF2 >> 1); i += 256) d[i] = s[i];
        __syncthreads();
    };

    loadB(BOFF2, 13 * 16 * 32);
    conv_pass<2, 0, 7>(sBF, X0, X1, lane, g0, g1);
    conv_pass<2, 7, 6>(sBF, X0, X1, lane, g0, g1);

    loadB(BOFF3, 13 * 24 * 32);
    conv_pass<3, 0, 7>(sBF, X0, X1, lane, g0 + 100, g1 + 100);
    conv_pass<3, 7, 6>(sBF, X0, X1, lane, g0 + 100, g1 + 100);

    loadB(BOFF4, 13 * 32 * 32);
    conv_pass<4, 0, 7>(sBF, X0, X1, lane, g0 + 200, g1 + 200);
    conv_pass<4, 7, 6>(sBF, X0, X1, lane, g0 + 200, g1 + 200);

    loadB(BOFF5, 13 * 40 * 32);
    conv_pass<5, 0, 7>(sBF, X0, X1, lane, g0 + 300, g1 + 300);
    conv_pass<5, 7, 6>(sBF, X0, X1, lane, g0 + 300, g1 + 300);
}

// ---------------------------------------------------------------------------
// Head: proj (400->128) + two highway layers (known-good from R1).
// ---------------------------------------------------------------------------
__global__ __launch_bounds__(256) void head_kernel(
    const float* __restrict__ wp,
    const float* __restrict__ tw0, const float* __restrict__ tb0,
    const float* __restrict__ tw1, const float* __restrict__ tb1,
    const float* __restrict__ gw0, const float* __restrict__ gb0,
    const float* __restrict__ gw1, const float* __restrict__ gb1,
    float* __restrict__ out)
{
    extern __shared__ float smemf[];
    float* sA = smemf;           // 32*400
    float* sB = sA + 12800;      // 8256
    float* sX = sB + 8256;       // 32*128

    int tid  = threadIdx.x;
    int lane = tid & 31, grp = tid >> 5;
    int tok0 = blockIdx.x * 32;

    for (int i = tid; i < 3200; i += 256)
        reinterpret_cast<float4*>(sA)[i] =
            reinterpret_cast<const float4*>(g_conv + tok0 * 400)[i];

    float xr[4][4];

    {
        float acc[4][4];
#pragma unroll
        for (int tt = 0; tt < 4; ++tt)
#pragma unroll
            for (int hi = 0; hi < 4; ++hi) acc[tt][hi] = 0.0f;

        for (int k0 = 0; k0 < 400; k0 += 40) {
            __syncthreads();
            for (int i = tid; i < 128 * 40; i += 256) {
                int h = i / 40, kk = i - h * 40;
                sB[kk * 129 + h] = wp[h * 400 + k0 + kk];
            }
            __syncthreads();
            for (int kk = 0; kk < 40; ++kk) {
                float w0 = sB[kk * 129 + lane];
                float w1 = sB[kk * 129 + lane + 32];
                float w2 = sB[kk * 129 + lane + 64];
                float w3 = sB[kk * 129 + lane + 96];
#pragma unroll
                for (int tt = 0; tt < 4; ++tt) {
                    float a = sA[(grp * 4 + tt) * 400 + k0 + kk];
                    acc[tt][0] = fmaf(a, w0, acc[tt][0]);
                    acc[tt][1] = fmaf(a, w1, acc[tt][1]);
                    acc[tt][2] = fmaf(a, w2, acc[tt][2]);
                    acc[tt][3] = fmaf(a, w3, acc[tt][3]);
                }
            }
        }
#pragma unroll
        for (int tt = 0; tt < 4; ++tt)
#pragma unroll
            for (int hi = 0; hi < 4; ++hi) {
                xr[tt][hi] = acc[tt][hi];
                sX[(grp * 4 + tt) * 128 + lane + 32 * hi] = acc[tt][hi];
            }
        __syncthreads();
    }

    auto layer = [&](const float* twq, const float* tbq,
                     const float* gwq, const float* gbq) {
        float at[4][4], ag[4][4];
#pragma unroll
        for (int tt = 0; tt < 4; ++tt)
#pragma unroll
            for (int hi = 0; hi < 4; ++hi) { at[tt][hi] = 0.0f; ag[tt][hi] = 0.0f; }

        for (int k0 = 0; k0 < 128; k0 += 32) {
            __syncthreads();
            for (int i = tid; i < 128 * 32; i += 256) {
                int h = i >> 5, kk = i & 31;
                sB[kk * 129 + h]        = twq[h * 128 + k0 + kk];
                sB[4128 + kk * 129 + h] = gwq[h * 128 + k0 + kk];
            }
            __syncthreads();
            for (int kk = 0; kk < 32; ++kk) {
                float wt0 = sB[kk * 129 + lane];
                float wt1 = sB[kk * 129 + lane + 32];
                float wt2 = sB[kk * 129 + lane + 64];
                float wt3 = sB[kk * 129 + lane + 96];
                float wg0 = sB[4128 + kk * 129 + lane];
                float wg1 = sB[4128 + kk * 129 + lane + 32];
                float wg2 = sB[4128 + kk * 129 + lane + 64];
                float wg3 = sB[4128 + kk * 129 + lane + 96];
#pragma unroll
                for (int tt = 0; tt < 4; ++tt) {
                    float a = sX[(grp * 4 + tt) * 128 + k0 + kk];
                    at[tt][0] = fmaf(a, wt0, at[tt][0]);
                    at[tt][1] = fmaf(a, wt1, at[tt][1]);
                    at[tt][2] = fmaf(a, wt2, at[tt][2]);
                    at[tt][3] = fmaf(a, wt3, at[tt][3]);
                    ag[tt][0] = fmaf(a, wg0, ag[tt][0]);
                    ag[tt][1] = fmaf(a, wg1, ag[tt][1]);
                    ag[tt][2] = fmaf(a, wg2, ag[tt][2]);
                    ag[tt][3] = fmaf(a, wg3, ag[tt][3]);
                }
            }
        }
        float tb4[4], gb4[4];
#pragma unroll
        for (int hi = 0; hi < 4; ++hi) {
            tb4[hi] = tbq[lane + 32 * hi];
            gb4[hi] = gbq[lane + 32 * hi];
        }
#pragma unroll
        for (int tt = 0; tt < 4; ++tt)
#pragma unroll
            for (int hi = 0; hi < 4; ++hi) {
                float g = 1.0f / (1.0f + __expf(-(ag[tt][hi] + gb4[hi])));
                float t = fmaxf(at[tt][hi] + tb4[hi], 0.0f);
                xr[tt][hi] = g * t + (1.0f - g) * xr[tt][hi];
            }
        __syncthreads();
#pragma unroll
        for (int tt = 0; tt < 4; ++tt)
#pragma unroll
            for (int hi = 0; hi < 4; ++hi)
                sX[(grp * 4 + tt) * 128 + lane + 32 * hi] = xr[tt][hi];
        __syncthreads();
    };

    layer(tw0, tb0, gw0, gb0);
    layer(tw1, tb1, gw1, gb1);

#pragma unroll
    for (int tt = 0; tt < 4; ++tt)
#pragma unroll
        for (int hi = 0; hi < 4; ++hi)
            out[(tok0 + grp * 4 + tt) * 128 + lane + 32 * hi] = xr[tt][hi];
}

// ---------------------------------------------------------------------------
extern "C" void kernel_launch(void* const* d_in, const int* in_sizes, int n_in,
                              void* d_out, int out_size) {
    const int*   idxs = (const int*)  d_in[0];
    const float* vecs = (const float*)d_in[1];
    const float* f2   = (const float*)d_in[2];
    const float* f3   = (const float*)d_in[3];
    const float* f4   = (const float*)d_in[4];
    const float* f5   = (const float*)d_in[5];
    const float* wp   = (const float*)d_in[6];
    const float* tw0  = (const float*)d_in[7];
    const float* tb0  = (const float*)d_in[8];
    const float* tw1  = (const float*)d_in[9];
    const float* tb1  = (const float*)d_in[10];
    const float* gw0  = (const float*)d_in[11];
    const float* gb0  = (const float*)d_in[12];
    const float* gw1  = (const float*)d_in[13];
    const float* gb1  = (const float*)d_in[14];
    float* out = (float*)d_out;

    size_t smem2 = (size_t)(12800 + 8256 + 4096) * 4;
    cudaFuncSetAttribute(conv_kernel, cudaFuncAttributeMaxDynamicSharedMemorySize, SM_TOT);
    cudaFuncSetAttribute(head_kernel, cudaFuncAttributeMaxDynamicSharedMemorySize, (int)smem2);

    prep_kernel<<<52, 128>>>(f2, f3, f4, f5);
    conv_kernel<<<1600, 256, SM_TOT>>>(idxs, vecs);
    head_kernel<<<800, 256, smem2>>>(wp, tw0, tb0, tw1, tb1,
                                     gw0, gb0, gw1, gb1, out);
}

// round 11
// speedup vs baseline: 3.3052x; 1.9506x over previous
#include <cuda_runtime.h>
#include <cuda_fp16.h>
#include <cstdint>

// ---------------------------------------------------------------------------
// CharacterEmbeddingLayer on GB300 (compute_103 PTX -> classic mma.sync only).
// Conv via fp16 m16n8k16 tensor cores (fp32 accum), 2 CTAs/SM:
//   per (token, window w): D[16 x 104] = A[16 x w*64] @ filt_w^T
//   A row l = X[l..l+w-1] contiguous in SMEM (fp16, stride 80 halfs).
//   k-permutation: logical {2t,2t+1,2t+8,2t+9} -> phys {4t..4t+3} so A pairs
//   and B fragments are contiguous LDS.64. B prepacked by prep_kernel.
//   Epilogue in-fragment: max over valid rows via shfl_xor, tanh, store fp32.
// Head: proj(400->128) + 2 highway layers (known-good fp32 scalar).
// ---------------------------------------------------------------------------

#define NTOK 25600
#define XSTR 80                  // X row stride in halfs (160B = 8 words mod 32)
#define XTOK (20 * XSTR)         // 20 rows/token (16 real + 4 zero pad)

// g_bfrag offsets in uint2 units: per window 13 ntiles x 4W ksteps x 32 lanes
#define BOFF2 0
#define BOFF3 3328
#define BOFF4 8320
#define BOFF5 14976
#define BTOT  23296

__device__ float g_conv[NTOK * 400];             // 40.96 MB scratch
__device__ __align__(16) uint2 g_bfrag[BTOT];    // prepacked fp16 B fragments

// smem (bytes): sBF [35840] | Xs [51200] | sIdx [1024]
#define SM_BF  0
#define SM_XS  35840
#define SM_IDX (35840 + 51200)
#define SM_TOT (SM_IDX + 1024)   // 88064 -> 2 CTAs/SM

__device__ __forceinline__ void mma16816(float& d0, float& d1, float& d2, float& d3,
                                         uint32_t a0, uint32_t a1, uint32_t a2, uint32_t a3,
                                         uint32_t b0, uint32_t b1) {
    asm volatile(
        "mma.sync.aligned.m16n8k16.row.col.f32.f16.f16.f32 "
        "{%0,%1,%2,%3}, {%4,%5,%6,%7}, {%8,%9}, {%0,%1,%2,%3};"
        : "+f"(d0), "+f"(d1), "+f"(d2), "+f"(d3)
        : "r"(a0), "r"(a1), "r"(a2), "r"(a3), "r"(b0), "r"(b1));
}

__device__ __forceinline__ float my_tanh(float x) {
    float ax = fabsf(x);
    float e  = __expf(2.0f * ax);
    float r  = 1.0f - 2.0f / (e + 1.0f);
    return copysignf(r, x);
}

__device__ __forceinline__ uint32_t pack_h2(float a, float b) {
    __half2 h = __floats2half2_rn(a, b);
    return *reinterpret_cast<uint32_t*>(&h);
}

// ---------------------------------------------------------------------------
// Prep: pack filters fp16 into fragment order.
// Lane (f = n*8 + lane/4, t = lane&3): b0 = filt[f][ks*16+4t, +1],
// b1 = filt[f][ks*16+4t+2, +3]  (phys k; matches A's k-permutation).
// ---------------------------------------------------------------------------
__global__ void prep_kernel(const float* __restrict__ f2, const float* __restrict__ f3,
                            const float* __restrict__ f4, const float* __restrict__ f5) {
    int b  = blockIdx.x;
    int wi = b / 13, n = b % 13;
    int W  = wi + 2;
    const float* fp = (wi == 0) ? f2 : (wi == 1) ? f3 : (wi == 2) ? f4 : f5;
    int woff = (wi == 0) ? BOFF2 : (wi == 1) ? BOFF3 : (wi == 2) ? BOFF4 : BOFF5;
    int K16 = 4 * W;
    for (int i = threadIdx.x; i < K16 * 32; i += blockDim.x) {
        int ks = i >> 5, lane = i & 31;
        int t = lane & 3, f = n * 8 + (lane >> 2);
        float4 v = make_float4(0.f, 0.f, 0.f, 0.f);
        if (f < 100)
            v = *reinterpret_cast<const float4*>(fp + f * (W * 64) + ks * 16 + 4 * t);
        uint2 o;
        o.x = pack_h2(v.x, v.y);
        o.y = pack_h2(v.z, v.w);
        g_bfrag[woff + (n * K16 + ks) * 32 + lane] = o;
    }
}

// ---------------------------------------------------------------------------
// One pass: NTN ntiles of window W (relative ntile 0..NTN-1), 2 tokens/warp.
// ---------------------------------------------------------------------------
template<int W, int NTN>
__device__ __forceinline__ void conv_pass(
    const uint2* __restrict__ sBF,
    const __half* __restrict__ X0p, const __half* __restrict__ X1p,
    int lane, int fbase, float* __restrict__ g0, float* __restrict__ g1)
{
    constexpr int L   = 17 - W;
    constexpr int K16 = 4 * W;
    int r = lane >> 2, t = lane & 3;

    float acc0[NTN][4], acc1[NTN][4];
#pragma unroll
    for (int n = 0; n < NTN; ++n)
#pragma unroll
        for (int q = 0; q < 4; ++q) { acc0[n][q] = 0.0f; acc1[n][q] = 0.0f; }

#pragma unroll 4
    for (int ks = 0; ks < K16; ++ks) {
        int d = (ks >> 2) * XSTR + (ks & 3) * 16;
        uint2 A0 = *(const uint2*)(X0p + d);            // {a0, a2} token0
        uint2 A1 = *(const uint2*)(X0p + d + 8 * XSTR); // {a1, a3} token0
        uint2 B0 = *(const uint2*)(X1p + d);
        uint2 B1 = *(const uint2*)(X1p + d + 8 * XSTR);
#pragma unroll
        for (int n = 0; n < NTN; ++n) {
            uint2 bf = sBF[(n * K16 + ks) * 32 + lane];
            mma16816(acc0[n][0], acc0[n][1], acc0[n][2], acc0[n][3],
                     A0.x, A1.x, A0.y, A1.y, bf.x, bf.y);
            mma16816(acc1[n][0], acc1[n][1], acc1[n][2], acc1[n][3],
                     B0.x, B1.x, B0.y, B1.y, bf.x, bf.y);
        }
    }

    bool v2 = (r + 8) < L;
#pragma unroll
    for (int n = 0; n < NTN; ++n) {
        float m0 = v2 ? fmaxf(acc0[n][0], acc0[n][2]) : acc0[n][0];
        float m1 = v2 ? fmaxf(acc0[n][1], acc0[n][3]) : acc0[n][1];
        float p0 = v2 ? fmaxf(acc1[n][0], acc1[n][2]) : acc1[n][0];
        float p1 = v2 ? fmaxf(acc1[n][1], acc1[n][3]) : acc1[n][1];
#pragma unroll
        for (int o = 4; o <= 16; o <<= 1) {
            m0 = fmaxf(m0, __shfl_xor_sync(0xffffffffu, m0, o));
            m1 = fmaxf(m1, __shfl_xor_sync(0xffffffffu, m1, o));
            p0 = fmaxf(p0, __shfl_xor_sync(0xffffffffu, p0, o));
            p1 = fmaxf(p1, __shfl_xor_sync(0xffffffffu, p1, o));
        }
        int f = fbase + n * 8 + 2 * t;
        if (r == 0 && f < 100) {
            *(float2*)(g0 + f) = make_float2(my_tanh(m0), my_tanh(m1));
            *(float2*)(g1 + f) = make_float2(my_tanh(p0), my_tanh(p1));
        }
    }
}

__global__ __launch_bounds__(256, 2) void conv_kernel(
    const int* __restrict__ idxs, const float* __restrict__ vecs)
{
    extern __shared__ __align__(16) char smem[];
    uint2*  sBF  = (uint2*)(smem + SM_BF);
    __half* Xs   = (__half*)(smem + SM_XS);
    int*    sIdx = (int*)(smem + SM_IDX);

    int tid  = threadIdx.x;
    int tok0 = blockIdx.x * 16;

    sIdx[tid] = idxs[tok0 * 16 + tid];
    __syncthreads();

    // gather X fp16: 16 tokens x 20 rows x 16 quad-half groups
    for (int i = tid; i < 16 * 20 * 16; i += 256) {
        int tok = i / 320, rem = i % 320, row = rem >> 4, e4 = rem & 15;
        float4 v = make_float4(0.f, 0.f, 0.f, 0.f);
        if (row < 16) {
            int ci = sIdx[tok * 16 + row];
            v = *(const float4*)(vecs + ci * 64 + e4 * 4);
        }
        uint2 o;
        o.x = pack_h2(v.x, v.y);
        o.y = pack_h2(v.z, v.w);
        *(uint2*)(Xs + tok * XTOK + row * XSTR + e4 * 4) = o;
    }

    int warp = tid >> 5, lane = tid & 31;
    int r = lane >> 2, t = lane & 3;
    const __half* X0p = Xs + (warp * 2 + 0) * XTOK + r * XSTR + 4 * t;
    const __half* X1p = Xs + (warp * 2 + 1) * XTOK + r * XSTR + 4 * t;
    float* g0 = g_conv + (tok0 + warp * 2 + 0) * 400;
    float* g1 = g_conv + (tok0 + warp * 2 + 1) * 400;

    // load B chunk [nt0, nt0+ntn) of window woff into sBF
    auto loadB = [&](int woffU2, int K16, int nt0, int ntn) {
        __syncthreads();                  // prior consumers done (+X writes 1st time)
        const float4* s = (const float4*)(g_bfrag + woffU2 + nt0 * K16 * 32);
        float4* d = (float4*)sBF;
        int cnt = ntn * K16 * 16;         // float4 count
        for (int i = tid; i < cnt; i += 256) d[i] = s[i];
        __syncthreads();
    };

    loadB(BOFF2,  8, 0, 7); conv_pass<2, 7>(sBF, X0p, X1p, lane,  0, g0, g1);
    loadB(BOFF2,  8, 7, 6); conv_pass<2, 6>(sBF, X0p, X1p, lane, 56, g0, g1);

    loadB(BOFF3, 12, 0, 7); conv_pass<3, 7>(sBF, X0p, X1p, lane,  0, g0 + 100, g1 + 100);
    loadB(BOFF3, 12, 7, 6); conv_pass<3, 6>(sBF, X0p, X1p, lane, 56, g0 + 100, g1 + 100);

    loadB(BOFF4, 16, 0, 7); conv_pass<4, 7>(sBF, X0p, X1p, lane,  0, g0 + 200, g1 + 200);
    loadB(BOFF4, 16, 7, 6); conv_pass<4, 6>(sBF, X0p, X1p, lane, 56, g0 + 200, g1 + 200);

    loadB(BOFF5, 20, 0, 7); conv_pass<5, 7>(sBF, X0p, X1p, lane,  0, g0 + 300, g1 + 300);
    loadB(BOFF5, 20, 7, 6); conv_pass<5, 6>(sBF, X0p, X1p, lane, 56, g0 + 300, g1 + 300);
}

// ---------------------------------------------------------------------------
// Head: proj (400->128) + two highway layers (known-good fp32 scalar).
// ---------------------------------------------------------------------------
__global__ __launch_bounds__(256) void head_kernel(
    const float* __restrict__ wp,
    const float* __restrict__ tw0, const float* __restrict__ tb0,
    const float* __restrict__ tw1, const float* __restrict__ tb1,
    const float* __restrict__ gw0, const float* __restrict__ gb0,
    const float* __restrict__ gw1, const float* __restrict__ gb1,
    float* __restrict__ out)
{
    extern __shared__ float smemf[];
    float* sA = smemf;           // 32*400
    float* sB = sA + 12800;      // 8256
    float* sX = sB + 8256;       // 32*128

    int tid  = threadIdx.x;
    int lane = tid & 31, grp = tid >> 5;
    int tok0 = blockIdx.x * 32;

    for (int i = tid; i < 3200; i += 256)
        reinterpret_cast<float4*>(sA)[i] =
            reinterpret_cast<const float4*>(g_conv + tok0 * 400)[i];

    float xr[4][4];

    {
        float acc[4][4];
#pragma unroll
        for (int tt = 0; tt < 4; ++tt)
#pragma unroll
            for (int hi = 0; hi < 4; ++hi) acc[tt][hi] = 0.0f;

        for (int k0 = 0; k0 < 400; k0 += 40) {
            __syncthreads();
            for (int i = tid; i < 128 * 40; i += 256) {
                int h = i / 40, kk = i - h * 40;
                sB[kk * 129 + h] = wp[h * 400 + k0 + kk];
            }
            __syncthreads();
            for (int kk = 0; kk < 40; ++kk) {
                float w0 = sB[kk * 129 + lane];
                float w1 = sB[kk * 129 + lane + 32];
                float w2 = sB[kk * 129 + lane + 64];
                float w3 = sB[kk * 129 + lane + 96];
#pragma unroll
                for (int tt = 0; tt < 4; ++tt) {
                    float a = sA[(grp * 4 + tt) * 400 + k0 + kk];
                    acc[tt][0] = fmaf(a, w0, acc[tt][0]);
                    acc[tt][1] = fmaf(a, w1, acc[tt][1]);
                    acc[tt][2] = fmaf(a, w2, acc[tt][2]);
                    acc[tt][3] = fmaf(a, w3, acc[tt][3]);
                }
            }
        }
#pragma unroll
        for (int tt = 0; tt < 4; ++tt)
#pragma unroll
            for (int hi = 0; hi < 4; ++hi) {
                xr[tt][hi] = acc[tt][hi];
                sX[(grp * 4 + tt) * 128 + lane + 32 * hi] = acc[tt][hi];
            }
        __syncthreads();
    }

    auto layer = [&](const float* twq, const float* tbq,
                     const float* gwq, const float* gbq) {
        float at[4][4], ag[4][4];
#pragma unroll
        for (int tt = 0; tt < 4; ++tt)
#pragma unroll
            for (int hi = 0; hi < 4; ++hi) { at[tt][hi] = 0.0f; ag[tt][hi] = 0.0f; }

        for (int k0 = 0; k0 < 128; k0 += 32) {
            __syncthreads();
            for (int i = tid; i < 128 * 32; i += 256) {
                int h = i >> 5, kk = i & 31;
                sB[kk * 129 + h]        = twq[h * 128 + k0 + kk];
                sB[4128 + kk * 129 + h] = gwq[h * 128 + k0 + kk];
            }
            __syncthreads();
            for (int kk = 0; kk < 32; ++kk) {
                float wt0 = sB[kk * 129 + lane];
                float wt1 = sB[kk * 129 + lane + 32];
                float wt2 = sB[kk * 129 + lane + 64];
                float wt3 = sB[kk * 129 + lane + 96];
                float wg0 = sB[4128 + kk * 129 + lane];
                float wg1 = sB[4128 + kk * 129 + lane + 32];
                float wg2 = sB[4128 + kk * 129 + lane + 64];
                float wg3 = sB[4128 + kk * 129 + lane + 96];
#pragma unroll
                for (int tt = 0; tt < 4; ++tt) {
                    float a = sX[(grp * 4 + tt) * 128 + k0 + kk];
                    at[tt][0] = fmaf(a, wt0, at[tt][0]);
                    at[tt][1] = fmaf(a, wt1, at[tt][1]);
                    at[tt][2] = fmaf(a, wt2, at[tt][2]);
                    at[tt][3] = fmaf(a, wt3, at[tt][3]);
                    ag[tt][0] = fmaf(a, wg0, ag[tt][0]);
                    ag[tt][1] = fmaf(a, wg1, ag[tt][1]);
                    ag[tt][2] = fmaf(a, wg2, ag[tt][2]);
                    ag[tt][3] = fmaf(a, wg3, ag[tt][3]);
                }
            }
        }
        float tb4[4], gb4[4];
#pragma unroll
        for (int hi = 0; hi < 4; ++hi) {
            tb4[hi] = tbq[lane + 32 * hi];
            gb4[hi] = gbq[lane + 32 * hi];
        }
#pragma unroll
        for (int tt = 0; tt < 4; ++tt)
#pragma unroll
            for (int hi = 0; hi < 4; ++hi) {
                float g = 1.0f / (1.0f + __expf(-(ag[tt][hi] + gb4[hi])));
                float t = fmaxf(at[tt][hi] + tb4[hi], 0.0f);
                xr[tt][hi] = g * t + (1.0f - g) * xr[tt][hi];
            }
        __syncthreads();
#pragma unroll
        for (int tt = 0; tt < 4; ++tt)
#pragma unroll
            for (int hi = 0; hi < 4; ++hi)
                sX[(grp * 4 + tt) * 128 + lane + 32 * hi] = xr[tt][hi];
        __syncthreads();
    };

    layer(tw0, tb0, gw0, gb0);
    layer(tw1, tb1, gw1, gb1);

#pragma unroll
    for (int tt = 0; tt < 4; ++tt)
#pragma unroll
        for (int hi = 0; hi < 4; ++hi)
            out[(tok0 + grp * 4 + tt) * 128 + lane + 32 * hi] = xr[tt][hi];
}

// ---------------------------------------------------------------------------
extern "C" void kernel_launch(void* const* d_in, const int* in_sizes, int n_in,
                              void* d_out, int out_size) {
    const int*   idxs = (const int*)  d_in[0];
    const float* vecs = (const float*)d_in[1];
    const float* f2   = (const float*)d_in[2];
    const float* f3   = (const float*)d_in[3];
    const float* f4   = (const float*)d_in[4];
    const float* f5   = (const float*)d_in[5];
    const float* wp   = (const float*)d_in[6];
    const float* tw0  = (const float*)d_in[7];
    const float* tb0  = (const float*)d_in[8];
    const float* tw1  = (const float*)d_in[9];
    const float* tb1  = (const float*)d_in[10];
    const float* gw0  = (const float*)d_in[11];
    const float* gb0  = (const float*)d_in[12];
    const float* gw1  = (const float*)d_in[13];
    const float* gb1  = (const float*)d_in[14];
    float* out = (float*)d_out;

    size_t smem2 = (size_t)(12800 + 8256 + 4096) * 4;
    cudaFuncSetAttribute(conv_kernel, cudaFuncAttributeMaxDynamicSharedMemorySize, SM_TOT);
    cudaFuncSetAttribute(head_kernel, cudaFuncAttributeMaxDynamicSharedMemorySize, (int)smem2);

    prep_kernel<<<52, 128>>>(f2, f3, f4, f5);
    conv_kernel<<<1600, 256, SM_TOT>>>(idxs, vecs);
    head_kernel<<<800, 256, smem2>>>(wp, tw0, tb0, tw1, tb1,
                                     gw0, gb0, gw1, gb1, out);
}